// round 7
// baseline (speedup 1.0000x reference)
#include <cuda_runtime.h>
#include <cuda_bf16.h>
#include <cstdint>

#define NROWS 8192
#define DIM   128
#define CHUNK 128                  // samples per tile
#define NBLOCKS 128                // b<64: X chunk b (+diag); b>=64: Y chunk b-64
#define NTHREADS 1024              // 32 warps -> occ 50%, 64-reg budget

// ---------------- device-global scratch (no allocations allowed) -----------
// Zero at load; every launch restores the zeroed state before exiting.
__device__ float    g_G[2][DIM * DIM];  // [0]=X^T X, [1]=Y^T Y
__device__ float    g_S2;               // sum d_i^2
__device__ float    g_S3;               // sum d_i
__device__ unsigned g_ticket;

// ---------------- helpers ---------------------------------------------------
__device__ __forceinline__ uint32_t smem_u32(const void* p) {
    uint32_t a;
    asm("{ .reg .u64 t; cvta.to.shared.u64 t, %1; cvt.u32.u64 %0, t; }" : "=r"(a) : "l"(p));
    return a;
}

// Tile stored SAMPLE-major: S[k][d]; two 16KB subtiles by d>>6; SW128 swizzle.
__device__ __forceinline__ uint32_t toff(int k, int d) {
    uint32_t o = (uint32_t)(k * 128 + (d & 63) * 2);
    o ^= (o >> 3) & 0x70;
    return (uint32_t)((d >> 6) * 16384) + o;
}

#define LO_OFF     32768           // lo tile after hi tile (each 32KB)
#define SMEM_TOTAL 65536

__device__ __forceinline__ void ldsm4t(uint32_t* r, uint32_t addr) {
    asm volatile("ldmatrix.sync.aligned.m8n8.x4.trans.shared.b16 {%0,%1,%2,%3}, [%4];"
                 : "=r"(r[0]), "=r"(r[1]), "=r"(r[2]), "=r"(r[3]) : "r"(addr));
}

__device__ __forceinline__ void mma_bf16(float* d, const uint32_t* a,
                                         uint32_t b0, uint32_t b1) {
    asm volatile(
        "mma.sync.aligned.m16n8k16.row.col.f32.bf16.bf16.f32 "
        "{%0,%1,%2,%3}, {%4,%5,%6,%7}, {%8,%9}, {%0,%1,%2,%3};"
        : "+f"(d[0]), "+f"(d[1]), "+f"(d[2]), "+f"(d[3])
        : "r"(a[0]), "r"(a[1]), "r"(a[2]), "r"(a[3]), "r"(b0), "r"(b1));
}

// Non-returning vector atomic add (sm_90+).
__device__ __forceinline__ void red_add_v2(float* p, float a, float b) {
    asm volatile("red.global.add.v2.f32 [%0], {%1, %2};"
                 :: "l"(p), "f"(a), "f"(b) : "memory");
}

// ---------------------------------------------------------------------------
// Single fused kernel, 32 warps: warp w owns output slab
// rows [(w&7)*16, +16) x cols [(w>>3)*32, +32).
// ---------------------------------------------------------------------------
__global__ __launch_bounds__(NTHREADS, 1)
void gram_all(const float* __restrict__ X, const float* __restrict__ Y,
              float* __restrict__ out) {
    extern __shared__ char smem[];
    __shared__ double   sred[NTHREADS];
    __shared__ unsigned s_last;

    const uint32_t sb = smem_u32(smem);
    const int tid  = threadIdx.x;
    const int w    = tid >> 5;
    const int lane = tid & 31;

    const bool isX  = blockIdx.x < (NBLOCKS / 2);
    const int chunk = isX ? blockIdx.x : blockIdx.x - NBLOCKS / 2;
    const float* base  = (isX ? X : Y) + (size_t)chunk * CHUNK * DIM;
    const float* ybase = Y + (size_t)chunk * CHUNK * DIM;   // diag (X blocks)

    // ldmatrix per-lane tile-row selectors
    const int lr    = lane & 7;
    const int a_kad = (lane & 16) ? 8 : 0;
    const int a_mad = (lane & 8)  ? 8 : 0;
    const int b_kad = (lane & 8)  ? 8 : 0;
    const int b_nad = (lane & 16) ? 8 : 0;
    const int m0    = (w & 7) * 16;        // warp's output row slab
    const int nbase = (w >> 3) * 32;       // warp's output column quarter

    // ---- convert fp32 -> bf16 hi/lo tiles; X blocks also compute diag ----
    // Batch all global loads first (MLP), then the cvt chains.
    {
        float4 v[4], u[4];
        #pragma unroll
        for (int it = 0; it < 4; ++it)
            v[it] = *reinterpret_cast<const float4*>(base + (w + 32 * it) * DIM + lane * 4);
        if (isX) {
            #pragma unroll
            for (int it = 0; it < 4; ++it)
                u[it] = *reinterpret_cast<const float4*>(ybase + (w + 32 * it) * DIM + lane * 4);
        }

        float s2 = 0.0f, s3 = 0.0f;
        #pragma unroll
        for (int it = 0; it < 4; ++it) {
            const int r = w + 32 * it;                // sample row
            __nv_bfloat162 h01 = __floats2bfloat162_rn(v[it].x, v[it].y);
            __nv_bfloat162 h23 = __floats2bfloat162_rn(v[it].z, v[it].w);
            __nv_bfloat162 l01 = __floats2bfloat162_rn(v[it].x - __bfloat162float(h01.x),
                                                       v[it].y - __bfloat162float(h01.y));
            __nv_bfloat162 l23 = __floats2bfloat162_rn(v[it].z - __bfloat162float(h23.x),
                                                       v[it].w - __bfloat162float(h23.y));
            const uint32_t o = toff(r, lane * 4);
            uint2 hv, lv;
            hv.x = *reinterpret_cast<uint32_t*>(&h01);
            hv.y = *reinterpret_cast<uint32_t*>(&h23);
            lv.x = *reinterpret_cast<uint32_t*>(&l01);
            lv.y = *reinterpret_cast<uint32_t*>(&l23);
            *reinterpret_cast<uint2*>(smem + o)          = hv;
            *reinterpret_cast<uint2*>(smem + LO_OFF + o) = lv;

            if (isX) {                                // diag: d_r = <x_r, y_r>
                float d = v[it].x * u[it].x + v[it].y * u[it].y
                        + v[it].z * u[it].z + v[it].w * u[it].w;
                #pragma unroll
                for (int o2 = 16; o2; o2 >>= 1) d += __shfl_xor_sync(0xffffffffu, d, o2);
                s3 += d;
                s2 += d * d;
            }
        }
        if (isX && lane == 0) {
            atomicAdd(&g_S3, s3);
            atomicAdd(&g_S2, s2);
        }
    }
    __syncthreads();

    // ---- MMA mainloop: acc[nt][i], nt = 0..3 (8-col tiles in this quarter) ----
    float acc[4][4];
    #pragma unroll
    for (int nt = 0; nt < 4; ++nt)
        #pragma unroll
        for (int i = 0; i < 4; ++i) acc[nt][i] = 0.0f;

    #pragma unroll
    for (int ks = 0; ks < 8; ++ks) {
        const int k0 = ks * 16;
        uint32_t ahi[4], alo[4];
        const uint32_t aoff = toff(k0 + lr + a_kad, m0 + a_mad);
        ldsm4t(ahi, sb + aoff);
        ldsm4t(alo, sb + LO_OFF + aoff);

        #pragma unroll
        for (int ntp = 0; ntp < 2; ++ntp) {
            const int n0 = nbase + ntp * 16;
            uint32_t bhi[4], blo[4];
            const uint32_t boff = toff(k0 + lr + b_kad, n0 + b_nad);
            ldsm4t(bhi, sb + boff);
            ldsm4t(blo, sb + LO_OFF + boff);
            mma_bf16(acc[2 * ntp], ahi, bhi[0], bhi[1]);
            mma_bf16(acc[2 * ntp], ahi, blo[0], blo[1]);
            mma_bf16(acc[2 * ntp], alo, bhi[0], bhi[1]);
            mma_bf16(acc[2 * ntp + 1], ahi, bhi[2], bhi[3]);
            mma_bf16(acc[2 * ntp + 1], ahi, blo[2], blo[3]);
            mma_bf16(acc[2 * ntp + 1], alo, bhi[2], bhi[3]);
        }
    }

    // ---- merge partial Gram with v2 vector atomics ----
    {
        float* G = g_G[isX ? 0 : 1];
        const int row0 = m0 + (lane >> 2);
        const int col0 = (lane & 3) * 2;
        #pragma unroll
        for (int nt = 0; nt < 4; ++nt) {
            const int cc = nbase + nt * 8 + col0;
            red_add_v2(&G[row0 * DIM + cc],       acc[nt][0], acc[nt][1]);
            red_add_v2(&G[(row0 + 8) * DIM + cc], acc[nt][2], acc[nt][3]);
        }
    }

    // ---- ticket: last block finalizes ----
    __threadfence();
    if (tid == 0) s_last = atomicAdd(&g_ticket, 1u);
    __syncthreads();
    if (s_last != NBLOCKS - 1) return;
    __threadfence();   // acquire: all blocks' merges visible

    // Frobenius product <G0, G1> in double (4 float4 pairs per thread)
    const float4* G0 = reinterpret_cast<const float4*>(g_G[0]);
    const float4* G1 = reinterpret_cast<const float4*>(g_G[1]);
    double s1 = 0.0;
    #pragma unroll
    for (int j = 0; j < 4; ++j) {
        const int i = tid + NTHREADS * j;
        const float4 a = G0[i], b = G1[i];
        s1 += (double)a.x * b.x + (double)a.y * b.y
            + (double)a.z * b.z + (double)a.w * b.w;
    }
    sred[tid] = s1;
    __syncthreads();
    for (int s = NTHREADS / 2; s; s >>= 1) {
        if (tid < s) sred[tid] += sred[tid + s];
        __syncthreads();
    }
    if (tid == 0) {
        const double loss =
            (sred[0] - (double)g_S2) / ((double)NROWS * (double)(NROWS - 1))
            - 2.0 * (double)g_S3 / (double)NROWS;
        out[0] = (float)loss;
    }

    // ---- re-zero scratch so the next graph replay starts clean ----
    float4 z = make_float4(0.f, 0.f, 0.f, 0.f);
    float4* Z0 = reinterpret_cast<float4*>(g_G[0]);
    float4* Z1 = reinterpret_cast<float4*>(g_G[1]);
    #pragma unroll
    for (int j = 0; j < 4; ++j) {
        Z0[tid + NTHREADS * j] = z;
        Z1[tid + NTHREADS * j] = z;
    }
    if (tid == 0) { g_S2 = 0.0f; g_S3 = 0.0f; g_ticket = 0u; }
}

// ---------------------------------------------------------------------------
extern "C" void kernel_launch(void* const* d_in, const int* in_sizes, int n_in,
                              void* d_out, int out_size) {
    const float* X = (const float*)d_in[0];
    const float* Y = (const float*)d_in[1];
    float* out = (float*)d_out;

    static bool attr_set = false;   // idempotent host-side attribute
    if (!attr_set) {
        cudaFuncSetAttribute(gram_all,
                             cudaFuncAttributeMaxDynamicSharedMemorySize, SMEM_TOTAL);
        attr_set = true;
    }

    gram_all<<<NBLOCKS, NTHREADS, SMEM_TOTAL>>>(X, Y, out);
}

// round 8
// speedup vs baseline: 1.0544x; 1.0544x over previous
#include <cuda_runtime.h>
#include <cuda_bf16.h>
#include <cstdint>

#define NROWS 8192
#define DIM   128
#define CHUNK 128                  // samples per tile
#define NBLOCKS 128                // b<64: X chunk b (+diag); b>=64: Y chunk b-64
#define NTHREADS 512               // 16 warps (best measured shape, R6)

// ---------------- device-global scratch (no allocations allowed) -----------
// Zero at load; finalize restores the zeroed state every launch.
__device__ float    g_G[2][DIM * DIM];  // [0]=X^T X, [1]=Y^T Y
__device__ float    g_S2;               // sum d_i^2
__device__ float    g_S3;               // sum d_i

// ---------------- helpers ---------------------------------------------------
__device__ __forceinline__ uint32_t smem_u32(const void* p) {
    uint32_t a;
    asm("{ .reg .u64 t; cvta.to.shared.u64 t, %1; cvt.u32.u64 %0, t; }" : "=r"(a) : "l"(p));
    return a;
}

// Tile stored SAMPLE-major: S[k][d]; two 16KB subtiles by d>>6; SW128 swizzle.
__device__ __forceinline__ uint32_t toff(int k, int d) {
    uint32_t o = (uint32_t)(k * 128 + (d & 63) * 2);
    o ^= (o >> 3) & 0x70;
    return (uint32_t)((d >> 6) * 16384) + o;
}

#define LO_OFF     32768           // lo tile after hi tile (each 32KB)
#define SMEM_TOTAL 65536

__device__ __forceinline__ void ldsm4t(uint32_t* r, uint32_t addr) {
    asm volatile("ldmatrix.sync.aligned.m8n8.x4.trans.shared.b16 {%0,%1,%2,%3}, [%4];"
                 : "=r"(r[0]), "=r"(r[1]), "=r"(r[2]), "=r"(r[3]) : "r"(addr));
}

__device__ __forceinline__ void mma_bf16(float* d, const uint32_t* a,
                                         uint32_t b0, uint32_t b1) {
    asm volatile(
        "mma.sync.aligned.m16n8k16.row.col.f32.bf16.bf16.f32 "
        "{%0,%1,%2,%3}, {%4,%5,%6,%7}, {%8,%9}, {%0,%1,%2,%3};"
        : "+f"(d[0]), "+f"(d[1]), "+f"(d[2]), "+f"(d[3])
        : "r"(a[0]), "r"(a[1]), "r"(a[2]), "r"(a[3]), "r"(b0), "r"(b1));
}

// Non-returning vector atomic add (sm_90+).
__device__ __forceinline__ void red_add_v2(float* p, float a, float b) {
    asm volatile("red.global.add.v2.f32 [%0], {%1, %2};"
                 :: "l"(p), "f"(a), "f"(b) : "memory");
}

// ---------------------------------------------------------------------------
// Kernel 1: convert(+diag) -> tensor-core Gram -> vec-atomic merge -> exit.
// 16 warps: warp w owns rows [(w&7)*16, +16) x cols [(w>>3)*64, +64).
// ---------------------------------------------------------------------------
__global__ __launch_bounds__(NTHREADS, 1)
void gram_diag(const float* __restrict__ X, const float* __restrict__ Y) {
    extern __shared__ char smem[];
    const uint32_t sb = smem_u32(smem);
    const int tid  = threadIdx.x;
    const int w    = tid >> 5;
    const int lane = tid & 31;

    const bool isX  = blockIdx.x < (NBLOCKS / 2);
    const int chunk = isX ? blockIdx.x : blockIdx.x - NBLOCKS / 2;
    const float* base  = (isX ? X : Y) + (size_t)chunk * CHUNK * DIM;
    const float* ybase = Y + (size_t)chunk * CHUNK * DIM;   // diag (X blocks)

    // ldmatrix per-lane tile-row selectors
    const int lr    = lane & 7;
    const int a_kad = (lane & 16) ? 8 : 0;
    const int a_mad = (lane & 8)  ? 8 : 0;
    const int b_kad = (lane & 8)  ? 8 : 0;
    const int b_nad = (lane & 16) ? 8 : 0;
    const int m0    = (w & 7) * 16;        // warp's output row slab
    const int nbase = (w >> 3) * 64;       // warp's output column half

    // ---- convert fp32 -> bf16 hi/lo tiles; X blocks also compute diag ----
    float s2 = 0.0f, s3 = 0.0f;
    #pragma unroll
    for (int it = 0; it < 8; ++it) {
        const int r = w + 16 * it;                    // sample row
        const float4 v = *reinterpret_cast<const float4*>(base + r * DIM + lane * 4);
        __nv_bfloat162 h01 = __floats2bfloat162_rn(v.x, v.y);
        __nv_bfloat162 h23 = __floats2bfloat162_rn(v.z, v.w);
        __nv_bfloat162 l01 = __floats2bfloat162_rn(v.x - __bfloat162float(h01.x),
                                                   v.y - __bfloat162float(h01.y));
        __nv_bfloat162 l23 = __floats2bfloat162_rn(v.z - __bfloat162float(h23.x),
                                                   v.w - __bfloat162float(h23.y));
        const uint32_t o = toff(r, lane * 4);
        uint2 hv, lv;
        hv.x = *reinterpret_cast<uint32_t*>(&h01);
        hv.y = *reinterpret_cast<uint32_t*>(&h23);
        lv.x = *reinterpret_cast<uint32_t*>(&l01);
        lv.y = *reinterpret_cast<uint32_t*>(&l23);
        *reinterpret_cast<uint2*>(smem + o)          = hv;
        *reinterpret_cast<uint2*>(smem + LO_OFF + o) = lv;

        if (isX) {                                    // diag: d_r = <x_r, y_r>
            const float4 u = *reinterpret_cast<const float4*>(ybase + r * DIM + lane * 4);
            float d = v.x * u.x + v.y * u.y + v.z * u.z + v.w * u.w;
            #pragma unroll
            for (int o2 = 16; o2; o2 >>= 1) d += __shfl_xor_sync(0xffffffffu, d, o2);
            s3 += d;
            s2 += d * d;
        }
    }
    if (isX && lane == 0) {
        atomicAdd(&g_S3, s3);
        atomicAdd(&g_S2, s2);
    }
    __syncthreads();

    // ---- MMA mainloop: acc[nt][i], nt = 0..7 (8-col tiles in this half) ----
    float acc[8][4];
    #pragma unroll
    for (int nt = 0; nt < 8; ++nt)
        #pragma unroll
        for (int i = 0; i < 4; ++i) acc[nt][i] = 0.0f;

    for (int ks = 0; ks < 8; ++ks) {
        const int k0 = ks * 16;
        uint32_t ahi[4], alo[4];
        const uint32_t aoff = toff(k0 + lr + a_kad, m0 + a_mad);
        ldsm4t(ahi, sb + aoff);
        ldsm4t(alo, sb + LO_OFF + aoff);

        #pragma unroll
        for (int ntp = 0; ntp < 4; ++ntp) {
            const int n0 = nbase + ntp * 16;
            uint32_t bhi[4], blo[4];
            const uint32_t boff = toff(k0 + lr + b_kad, n0 + b_nad);
            ldsm4t(bhi, sb + boff);
            ldsm4t(blo, sb + LO_OFF + boff);
            mma_bf16(acc[2 * ntp], ahi, bhi[0], bhi[1]);
            mma_bf16(acc[2 * ntp], ahi, blo[0], blo[1]);
            mma_bf16(acc[2 * ntp], alo, bhi[0], bhi[1]);
            mma_bf16(acc[2 * ntp + 1], ahi, bhi[2], bhi[3]);
            mma_bf16(acc[2 * ntp + 1], ahi, blo[2], blo[3]);
            mma_bf16(acc[2 * ntp + 1], alo, bhi[2], bhi[3]);
        }
    }

    // ---- merge partial Gram with v2 vector atomics; kernel end = sync ----
    float* G = g_G[isX ? 0 : 1];
    const int row0 = m0 + (lane >> 2);
    const int col0 = (lane & 3) * 2;
    #pragma unroll
    for (int nt = 0; nt < 8; ++nt) {
        const int cc = nbase + nt * 8 + col0;
        red_add_v2(&G[row0 * DIM + cc],       acc[nt][0], acc[nt][1]);
        red_add_v2(&G[(row0 + 8) * DIM + cc], acc[nt][2], acc[nt][3]);
    }
}

// ---------------------------------------------------------------------------
// Kernel 2: Frobenius product + combine + write + re-zero. 1 block x 1024.
// ---------------------------------------------------------------------------
__global__ __launch_bounds__(1024, 1)
void finalize(float* __restrict__ out) {
    __shared__ double wsum[32];
    const int tid  = threadIdx.x;
    const int lane = tid & 31;
    const int w    = tid >> 5;

    // 16384 floats per matrix = 4096 float4; 4 per thread.
    const float4* G0 = reinterpret_cast<const float4*>(g_G[0]);
    const float4* G1 = reinterpret_cast<const float4*>(g_G[1]);
    double s1 = 0.0;
    #pragma unroll
    for (int j = 0; j < 4; ++j) {
        const int i = tid + 1024 * j;
        const float4 a = G0[i], b = G1[i];
        s1 += (double)a.x * b.x + (double)a.y * b.y
            + (double)a.z * b.z + (double)a.w * b.w;
    }
    #pragma unroll
    for (int o = 16; o; o >>= 1) s1 += __shfl_xor_sync(0xffffffffu, s1, o);
    if (lane == 0) wsum[w] = s1;
    __syncthreads();
    if (w == 0) {
        double t = wsum[lane];
        #pragma unroll
        for (int o = 16; o; o >>= 1) t += __shfl_xor_sync(0xffffffffu, t, o);
        if (lane == 0) {
            const double loss =
                (t - (double)g_S2) / ((double)NROWS * (double)(NROWS - 1))
                - 2.0 * (double)g_S3 / (double)NROWS;
            out[0] = (float)loss;
        }
    }
    __syncthreads();   // everyone past the reads before scratch reset

    // ---- re-zero scratch for the next graph replay ----
    float4 z = make_float4(0.f, 0.f, 0.f, 0.f);
    float4* Z0 = reinterpret_cast<float4*>(g_G[0]);
    float4* Z1 = reinterpret_cast<float4*>(g_G[1]);
    #pragma unroll
    for (int j = 0; j < 4; ++j) {
        Z0[tid + 1024 * j] = z;
        Z1[tid + 1024 * j] = z;
    }
    if (tid == 0) { g_S2 = 0.0f; g_S3 = 0.0f; }
}

// ---------------------------------------------------------------------------
extern "C" void kernel_launch(void* const* d_in, const int* in_sizes, int n_in,
                              void* d_out, int out_size) {
    const float* X = (const float*)d_in[0];
    const float* Y = (const float*)d_in[1];
    float* out = (float*)d_out;

    static bool attr_set = false;   // idempotent host-side attribute
    if (!attr_set) {
        cudaFuncSetAttribute(gram_diag,
                             cudaFuncAttributeMaxDynamicSharedMemorySize, SMEM_TOTAL);
        attr_set = true;
    }

    gram_diag<<<NBLOCKS, NTHREADS, SMEM_TOTAL>>>(X, Y);
    finalize<<<1, 1024>>>(out);
}

// round 9
// speedup vs baseline: 1.8400x; 1.7450x over previous
#include <cuda_runtime.h>
#include <cuda_bf16.h>
#include <cstdint>

#define NROWS 8192
#define DIM   128
#define CHUNK 128                  // samples per tile
#define NBLOCKS 128                // b<64: X chunk b (+diag); b>=64: Y chunk b-64
#define NTHREADS 512               // 16 warps

// ---------------- device-global scratch (no allocations allowed) -----------
// Zero at load; the kernel restores the zeroed state before exiting.
__device__ float    g_G[2][DIM * DIM];  // [0]=X^T X, [1]=Y^T Y
__device__ float    g_S2;               // sum d_i^2
__device__ float    g_S3;               // sum d_i
__device__ unsigned g_ticket;

// ---------------- helpers ---------------------------------------------------
__device__ __forceinline__ uint32_t smem_u32(const void* p) {
    uint32_t a;
    asm("{ .reg .u64 t; cvta.to.shared.u64 t, %1; cvt.u32.u64 %0, t; }" : "=r"(a) : "l"(p));
    return a;
}

// Tile stored SAMPLE-major: S[k][d]; two 16KB subtiles by d>>6; SW128 swizzle.
__device__ __forceinline__ uint32_t toff(int k, int d) {
    uint32_t o = (uint32_t)(k * 128 + (d & 63) * 2);
    o ^= (o >> 3) & 0x70;
    return (uint32_t)((d >> 6) * 16384) + o;
}

#define LO_OFF     32768           // lo tile after hi tile (each 32KB)
#define SMEM_TOTAL 65536

__device__ __forceinline__ void ldsm4t(uint32_t* r, uint32_t addr) {
    asm volatile("ldmatrix.sync.aligned.m8n8.x4.trans.shared.b16 {%0,%1,%2,%3}, [%4];"
                 : "=r"(r[0]), "=r"(r[1]), "=r"(r[2]), "=r"(r[3]) : "r"(addr));
}

__device__ __forceinline__ void mma_bf16(float* d, const uint32_t* a,
                                         uint32_t b0, uint32_t b1) {
    asm volatile(
        "mma.sync.aligned.m16n8k16.row.col.f32.bf16.bf16.f32 "
        "{%0,%1,%2,%3}, {%4,%5,%6,%7}, {%8,%9}, {%0,%1,%2,%3};"
        : "+f"(d[0]), "+f"(d[1]), "+f"(d[2]), "+f"(d[3])
        : "r"(a[0]), "r"(a[1]), "r"(a[2]), "r"(a[3]), "r"(b0), "r"(b1));
}

// Non-returning vector atomic add (sm_90+).
__device__ __forceinline__ void red_add_v2(float* p, float a, float b) {
    asm volatile("red.global.add.v2.f32 [%0], {%1, %2};"
                 :: "l"(p), "f"(a), "f"(b) : "memory");
}

// ---------------------------------------------------------------------------
// Single fused kernel: convert(+diag) -> tensor-core Gram -> red.v2 merge ->
// ticket -> last block: FLOAT Frobenius reduce + double scalar combine +
// re-zero. 16 warps: warp w owns rows [(w&7)*16,+16) x cols [(w>>3)*64,+64).
// ---------------------------------------------------------------------------
__global__ __launch_bounds__(NTHREADS, 1)
void gram_all(const float* __restrict__ X, const float* __restrict__ Y,
              float* __restrict__ out) {
    extern __shared__ char smem[];
    __shared__ float    wsum[16];
    __shared__ unsigned s_last;

    const uint32_t sb = smem_u32(smem);
    const int tid  = threadIdx.x;
    const int w    = tid >> 5;
    const int lane = tid & 31;

    const bool isX  = blockIdx.x < (NBLOCKS / 2);
    const int chunk = isX ? blockIdx.x : blockIdx.x - NBLOCKS / 2;
    const float* base  = (isX ? X : Y) + (size_t)chunk * CHUNK * DIM;
    const float* ybase = Y + (size_t)chunk * CHUNK * DIM;   // diag (X blocks)

    // ldmatrix per-lane tile-row selectors
    const int lr    = lane & 7;
    const int a_kad = (lane & 16) ? 8 : 0;
    const int a_mad = (lane & 8)  ? 8 : 0;
    const int b_kad = (lane & 8)  ? 8 : 0;
    const int b_nad = (lane & 16) ? 8 : 0;
    const int m0    = (w & 7) * 16;        // warp's output row slab
    const int nbase = (w >> 3) * 64;       // warp's output column half

    // ---- convert fp32 -> bf16 hi/lo tiles; X blocks also compute diag ----
    float s2 = 0.0f, s3 = 0.0f;
    #pragma unroll
    for (int it = 0; it < 8; ++it) {
        const int r = w + 16 * it;                    // sample row
        const float4 v = *reinterpret_cast<const float4*>(base + r * DIM + lane * 4);
        __nv_bfloat162 h01 = __floats2bfloat162_rn(v.x, v.y);
        __nv_bfloat162 h23 = __floats2bfloat162_rn(v.z, v.w);
        __nv_bfloat162 l01 = __floats2bfloat162_rn(v.x - __bfloat162float(h01.x),
                                                   v.y - __bfloat162float(h01.y));
        __nv_bfloat162 l23 = __floats2bfloat162_rn(v.z - __bfloat162float(h23.x),
                                                   v.w - __bfloat162float(h23.y));
        const uint32_t o = toff(r, lane * 4);
        uint2 hv, lv;
        hv.x = *reinterpret_cast<uint32_t*>(&h01);
        hv.y = *reinterpret_cast<uint32_t*>(&h23);
        lv.x = *reinterpret_cast<uint32_t*>(&l01);
        lv.y = *reinterpret_cast<uint32_t*>(&l23);
        *reinterpret_cast<uint2*>(smem + o)          = hv;
        *reinterpret_cast<uint2*>(smem + LO_OFF + o) = lv;

        if (isX) {                                    // diag: d_r = <x_r, y_r>
            const float4 u = *reinterpret_cast<const float4*>(ybase + r * DIM + lane * 4);
            float d = v.x * u.x + v.y * u.y + v.z * u.z + v.w * u.w;
            #pragma unroll
            for (int o2 = 16; o2; o2 >>= 1) d += __shfl_xor_sync(0xffffffffu, d, o2);
            s3 += d;
            s2 += d * d;
        }
    }
    if (isX && lane == 0) {
        atomicAdd(&g_S3, s3);
        atomicAdd(&g_S2, s2);
    }
    __syncthreads();

    // ---- MMA mainloop: acc[nt][i], nt = 0..7 (8-col tiles in this half) ----
    float acc[8][4];
    #pragma unroll
    for (int nt = 0; nt < 8; ++nt)
        #pragma unroll
        for (int i = 0; i < 4; ++i) acc[nt][i] = 0.0f;

    for (int ks = 0; ks < 8; ++ks) {
        const int k0 = ks * 16;
        uint32_t ahi[4], alo[4];
        const uint32_t aoff = toff(k0 + lr + a_kad, m0 + a_mad);
        ldsm4t(ahi, sb + aoff);
        ldsm4t(alo, sb + LO_OFF + aoff);

        #pragma unroll
        for (int ntp = 0; ntp < 4; ++ntp) {
            const int n0 = nbase + ntp * 16;
            uint32_t bhi[4], blo[4];
            const uint32_t boff = toff(k0 + lr + b_kad, n0 + b_nad);
            ldsm4t(bhi, sb + boff);
            ldsm4t(blo, sb + LO_OFF + boff);
            mma_bf16(acc[2 * ntp], ahi, bhi[0], bhi[1]);
            mma_bf16(acc[2 * ntp], ahi, blo[0], blo[1]);
            mma_bf16(acc[2 * ntp], alo, bhi[0], bhi[1]);
            mma_bf16(acc[2 * ntp + 1], ahi, bhi[2], bhi[3]);
            mma_bf16(acc[2 * ntp + 1], ahi, blo[2], blo[3]);
            mma_bf16(acc[2 * ntp + 1], alo, bhi[2], bhi[3]);
        }
    }

    // ---- merge partial Gram with v2 vector atomics ----
    {
        float* G = g_G[isX ? 0 : 1];
        const int row0 = m0 + (lane >> 2);
        const int col0 = (lane & 3) * 2;
        #pragma unroll
        for (int nt = 0; nt < 8; ++nt) {
            const int cc = nbase + nt * 8 + col0;
            red_add_v2(&G[row0 * DIM + cc],       acc[nt][0], acc[nt][1]);
            red_add_v2(&G[(row0 + 8) * DIM + cc], acc[nt][2], acc[nt][3]);
        }
    }

    // ---- ticket: last block finalizes ----
    __threadfence();                       // release: reds visible before ticket
    __syncthreads();                       // all warps' reds issued
    if (tid == 0) s_last = atomicAdd(&g_ticket, 1u);
    __syncthreads();
    if (s_last != NBLOCKS - 1) return;
    __threadfence();                       // acquire: all blocks' merges visible

    // ---- FLOAT Frobenius product <G0,G1> (hierarchical; fp64 only at end) --
    const float4* G0 = reinterpret_cast<const float4*>(g_G[0]);
    const float4* G1 = reinterpret_cast<const float4*>(g_G[1]);
    float s1 = 0.0f;
    #pragma unroll
    for (int j = 0; j < 8; ++j) {          // 4096 float4 / 512 threads
        const int i = tid + NTHREADS * j;
        const float4 a = G0[i], b = G1[i];
        s1 += a.x * b.x + a.y * b.y + a.z * b.z + a.w * b.w;
    }
    #pragma unroll
    for (int o = 16; o; o >>= 1) s1 += __shfl_xor_sync(0xffffffffu, s1, o);
    if (lane == 0) wsum[w] = s1;
    __syncthreads();
    if (tid == 0) {
        float t = 0.0f;
        #pragma unroll
        for (int i = 0; i < 16; ++i) t += wsum[i];
        const double loss =
            ((double)t - (double)g_S2) / ((double)NROWS * (double)(NROWS - 1))
            - 2.0 * (double)g_S3 / (double)NROWS;
        out[0] = (float)loss;
    }
    __syncthreads();   // reads done before scratch reset

    // ---- re-zero scratch for the next graph replay ----
    float4 z = make_float4(0.f, 0.f, 0.f, 0.f);
    float4* Z0 = reinterpret_cast<float4*>(g_G[0]);
    float4* Z1 = reinterpret_cast<float4*>(g_G[1]);
    #pragma unroll
    for (int j = 0; j < 8; ++j) {
        Z0[tid + NTHREADS * j] = z;
        Z1[tid + NTHREADS * j] = z;
    }
    if (tid == 0) { g_S2 = 0.0f; g_S3 = 0.0f; g_ticket = 0u; }
}

// ---------------------------------------------------------------------------
extern "C" void kernel_launch(void* const* d_in, const int* in_sizes, int n_in,
                              void* d_out, int out_size) {
    const float* X = (const float*)d_in[0];
    const float* Y = (const float*)d_in[1];
    float* out = (float*)d_out;

    static bool attr_set = false;   // idempotent host-side attribute
    if (!attr_set) {
        cudaFuncSetAttribute(gram_all,
                             cudaFuncAttributeMaxDynamicSharedMemorySize, SMEM_TOTAL);
        attr_set = true;
    }

    gram_all<<<NBLOCKS, NTHREADS, SMEM_TOTAL>>>(X, Y, out);
}

// round 10
// speedup vs baseline: 1.8431x; 1.0017x over previous
#include <cuda_runtime.h>
#include <cuda_bf16.h>
#include <cstdint>

#define NROWS 8192
#define DIM   128
#define CHUNK 128                  // samples per tile
#define NBLOCKS 128                // b<64: X chunk b (+diag); b>=64: Y chunk b-64
#define NTHREADS 512               // 16 warps

// ---------------- device-global scratch (no allocations allowed) -----------
// Zero at load; finalize restores the zeroed state every launch.
__device__ float    g_G[2][DIM * DIM];  // [0]=X^T X, [1]=Y^T Y
__device__ float    g_S2;               // sum d_i^2
__device__ float    g_S3;               // sum d_i

// ---------------- helpers ---------------------------------------------------
__device__ __forceinline__ uint32_t smem_u32(const void* p) {
    uint32_t a;
    asm("{ .reg .u64 t; cvta.to.shared.u64 t, %1; cvt.u32.u64 %0, t; }" : "=r"(a) : "l"(p));
    return a;
}

// Tile stored SAMPLE-major: S[k][d]; two 16KB subtiles by d>>6; SW128 swizzle.
__device__ __forceinline__ uint32_t toff(int k, int d) {
    uint32_t o = (uint32_t)(k * 128 + (d & 63) * 2);
    o ^= (o >> 3) & 0x70;
    return (uint32_t)((d >> 6) * 16384) + o;
}

#define LO_OFF     32768           // lo tile after hi tile (each 32KB)
#define SMEM_TOTAL 65536

__device__ __forceinline__ void ldsm4t(uint32_t* r, uint32_t addr) {
    asm volatile("ldmatrix.sync.aligned.m8n8.x4.trans.shared.b16 {%0,%1,%2,%3}, [%4];"
                 : "=r"(r[0]), "=r"(r[1]), "=r"(r[2]), "=r"(r[3]) : "r"(addr));
}

__device__ __forceinline__ void mma_bf16(float* d, const uint32_t* a,
                                         uint32_t b0, uint32_t b1) {
    asm volatile(
        "mma.sync.aligned.m16n8k16.row.col.f32.bf16.bf16.f32 "
        "{%0,%1,%2,%3}, {%4,%5,%6,%7}, {%8,%9}, {%0,%1,%2,%3};"
        : "+f"(d[0]), "+f"(d[1]), "+f"(d[2]), "+f"(d[3])
        : "r"(a[0]), "r"(a[1]), "r"(a[2]), "r"(a[3]), "r"(b0), "r"(b1));
}

// Non-returning vector atomic add (sm_90+).
__device__ __forceinline__ void red_add_v2(float* p, float a, float b) {
    asm volatile("red.global.add.v2.f32 [%0], {%1, %2};"
                 :: "l"(p), "f"(a), "f"(b) : "memory");
}

// ---------------------------------------------------------------------------
// Kernel 1: convert(+diag) -> tensor-core Gram -> red.v2 merge -> exit.
// No fence/ticket/tail: the kernel boundary is the global sync.
// 16 warps: warp w owns rows [(w&7)*16, +16) x cols [(w>>3)*64, +64).
// ---------------------------------------------------------------------------
__global__ __launch_bounds__(NTHREADS, 1)
void gram_diag(const float* __restrict__ X, const float* __restrict__ Y) {
    extern __shared__ char smem[];
    const uint32_t sb = smem_u32(smem);
    const int tid  = threadIdx.x;
    const int w    = tid >> 5;
    const int lane = tid & 31;

    const bool isX  = blockIdx.x < (NBLOCKS / 2);
    const int chunk = isX ? blockIdx.x : blockIdx.x - NBLOCKS / 2;
    const float* base  = (isX ? X : Y) + (size_t)chunk * CHUNK * DIM;
    const float* ybase = Y + (size_t)chunk * CHUNK * DIM;   // diag (X blocks)

    // ldmatrix per-lane tile-row selectors
    const int lr    = lane & 7;
    const int a_kad = (lane & 16) ? 8 : 0;
    const int a_mad = (lane & 8)  ? 8 : 0;
    const int b_kad = (lane & 8)  ? 8 : 0;
    const int b_nad = (lane & 16) ? 8 : 0;
    const int m0    = (w & 7) * 16;        // warp's output row slab
    const int nbase = (w >> 3) * 64;       // warp's output column half

    // ---- convert fp32 -> bf16 hi/lo tiles; X blocks also compute diag ----
    float s2 = 0.0f, s3 = 0.0f;
    #pragma unroll
    for (int it = 0; it < 8; ++it) {
        const int r = w + 16 * it;                    // sample row
        const float4 v = *reinterpret_cast<const float4*>(base + r * DIM + lane * 4);
        __nv_bfloat162 h01 = __floats2bfloat162_rn(v.x, v.y);
        __nv_bfloat162 h23 = __floats2bfloat162_rn(v.z, v.w);
        __nv_bfloat162 l01 = __floats2bfloat162_rn(v.x - __bfloat162float(h01.x),
                                                   v.y - __bfloat162float(h01.y));
        __nv_bfloat162 l23 = __floats2bfloat162_rn(v.z - __bfloat162float(h23.x),
                                                   v.w - __bfloat162float(h23.y));
        const uint32_t o = toff(r, lane * 4);
        uint2 hv, lv;
        hv.x = *reinterpret_cast<uint32_t*>(&h01);
        hv.y = *reinterpret_cast<uint32_t*>(&h23);
        lv.x = *reinterpret_cast<uint32_t*>(&l01);
        lv.y = *reinterpret_cast<uint32_t*>(&l23);
        *reinterpret_cast<uint2*>(smem + o)          = hv;
        *reinterpret_cast<uint2*>(smem + LO_OFF + o) = lv;

        if (isX) {                                    // diag: d_r = <x_r, y_r>
            const float4 u = *reinterpret_cast<const float4*>(ybase + r * DIM + lane * 4);
            float d = v.x * u.x + v.y * u.y + v.z * u.z + v.w * u.w;
            #pragma unroll
            for (int o2 = 16; o2; o2 >>= 1) d += __shfl_xor_sync(0xffffffffu, d, o2);
            s3 += d;
            s2 += d * d;
        }
    }
    if (isX && lane == 0) {
        atomicAdd(&g_S3, s3);
        atomicAdd(&g_S2, s2);
    }
    __syncthreads();

    // ---- MMA mainloop: acc[nt][i], nt = 0..7 (8-col tiles in this half) ----
    float acc[8][4];
    #pragma unroll
    for (int nt = 0; nt < 8; ++nt)
        #pragma unroll
        for (int i = 0; i < 4; ++i) acc[nt][i] = 0.0f;

    for (int ks = 0; ks < 8; ++ks) {
        const int k0 = ks * 16;
        uint32_t ahi[4], alo[4];
        const uint32_t aoff = toff(k0 + lr + a_kad, m0 + a_mad);
        ldsm4t(ahi, sb + aoff);
        ldsm4t(alo, sb + LO_OFF + aoff);

        #pragma unroll
        for (int ntp = 0; ntp < 4; ++ntp) {
            const int n0 = nbase + ntp * 16;
            uint32_t bhi[4], blo[4];
            const uint32_t boff = toff(k0 + lr + b_kad, n0 + b_nad);
            ldsm4t(bhi, sb + boff);
            ldsm4t(blo, sb + LO_OFF + boff);
            mma_bf16(acc[2 * ntp], ahi, bhi[0], bhi[1]);
            mma_bf16(acc[2 * ntp], ahi, blo[0], blo[1]);
            mma_bf16(acc[2 * ntp], alo, bhi[0], bhi[1]);
            mma_bf16(acc[2 * ntp + 1], ahi, bhi[2], bhi[3]);
            mma_bf16(acc[2 * ntp + 1], ahi, blo[2], blo[3]);
            mma_bf16(acc[2 * ntp + 1], alo, bhi[2], bhi[3]);
        }
    }

    // ---- merge partial Gram with v2 vector atomics; kernel end = sync ----
    float* G = g_G[isX ? 0 : 1];
    const int row0 = m0 + (lane >> 2);
    const int col0 = (lane & 3) * 2;
    #pragma unroll
    for (int nt = 0; nt < 8; ++nt) {
        const int cc = nbase + nt * 8 + col0;
        red_add_v2(&G[row0 * DIM + cc],       acc[nt][0], acc[nt][1]);
        red_add_v2(&G[(row0 + 8) * DIM + cc], acc[nt][2], acc[nt][3]);
    }
}

// ---------------------------------------------------------------------------
// Kernel 2: FLOAT Frobenius product + double scalar combine + re-zero.
// 1 block x 1024 threads; fp64 touched only for the 5-op final combine.
// ---------------------------------------------------------------------------
__global__ __launch_bounds__(1024, 1)
void finalize(float* __restrict__ out) {
    __shared__ float wsum[32];
    const int tid  = threadIdx.x;
    const int lane = tid & 31;
    const int w    = tid >> 5;

    // 16384 floats per matrix = 4096 float4; 4 per thread.
    const float4* G0 = reinterpret_cast<const float4*>(g_G[0]);
    const float4* G1 = reinterpret_cast<const float4*>(g_G[1]);
    float s1 = 0.0f;
    #pragma unroll
    for (int j = 0; j < 4; ++j) {
        const int i = tid + 1024 * j;
        const float4 a = G0[i], b = G1[i];
        s1 += a.x * b.x + a.y * b.y + a.z * b.z + a.w * b.w;
    }
    #pragma unroll
    for (int o = 16; o; o >>= 1) s1 += __shfl_xor_sync(0xffffffffu, s1, o);
    if (lane == 0) wsum[w] = s1;
    __syncthreads();
    if (tid == 0) {
        float t = 0.0f;
        #pragma unroll
        for (int i = 0; i < 32; ++i) t += wsum[i];
        const double loss =
            ((double)t - (double)g_S2) / ((double)NROWS * (double)(NROWS - 1))
            - 2.0 * (double)g_S3 / (double)NROWS;
        out[0] = (float)loss;
    }
    __syncthreads();   // reads done before scratch reset

    // ---- re-zero scratch for the next graph replay ----
    float4 z = make_float4(0.f, 0.f, 0.f, 0.f);
    float4* Z0 = reinterpret_cast<float4*>(g_G[0]);
    float4* Z1 = reinterpret_cast<float4*>(g_G[1]);
    #pragma unroll
    for (int j = 0; j < 4; ++j) {
        Z0[tid + 1024 * j] = z;
        Z1[tid + 1024 * j] = z;
    }
    if (tid == 0) { g_S2 = 0.0f; g_S3 = 0.0f; }
}

// ---------------------------------------------------------------------------
extern "C" void kernel_launch(void* const* d_in, const int* in_sizes, int n_in,
                              void* d_out, int out_size) {
    const float* X = (const float*)d_in[0];
    const float* Y = (const float*)d_in[1];
    float* out = (float*)d_out;

    static bool attr_set = false;   // idempotent host-side attribute
    if (!attr_set) {
        cudaFuncSetAttribute(gram_diag,
                             cudaFuncAttributeMaxDynamicSharedMemorySize, SMEM_TOTAL);
        attr_set = true;
    }

    gram_diag<<<NBLOCKS, NTHREADS, SMEM_TOTAL>>>(X, Y);
    finalize<<<1, 1024>>>(out);
}

// round 11
// speedup vs baseline: 2.0909x; 1.1345x over previous
#include <cuda_runtime.h>
#include <cuda_bf16.h>
#include <cstdint>

#define NROWS 8192
#define DIM   128
#define CHUNK 128                  // samples per tile
#define NBLOCKS 128                // b<64: X chunk b (+diag); b>=64: Y chunk b-64
#define NTHREADS 512               // 16 warps
#define FIN_BLOCKS 16

// ---------------- device-global scratch (no allocations allowed) -----------
// Zero at load; finalize restores the zeroed state every launch.
// g_G holds P = H^T H + 2 H^T L per matrix (NOT the symmetric Gram; see S1 algebra).
__device__ float    g_G[2][DIM * DIM];
__device__ float    g_S1;               // <Px,Py>_F partial accumulator
__device__ float    g_S2;               // sum d_i^2
__device__ float    g_S3;               // sum d_i
__device__ unsigned g_ticket;

// ---------------- helpers ---------------------------------------------------
__device__ __forceinline__ uint32_t smem_u32(const void* p) {
    uint32_t a;
    asm("{ .reg .u64 t; cvta.to.shared.u64 t, %1; cvt.u32.u64 %0, t; }" : "=r"(a) : "l"(p));
    return a;
}

// Tile stored SAMPLE-major: S[k][d]; two 16KB subtiles by d>>6; SW128 swizzle.
__device__ __forceinline__ uint32_t toff(int k, int d) {
    uint32_t o = (uint32_t)(k * 128 + (d & 63) * 2);
    o ^= (o >> 3) & 0x70;
    return (uint32_t)((d >> 6) * 16384) + o;
}

#define LO_OFF     32768           // 2*lo tile after hi tile (each 32KB)
#define SMEM_TOTAL 65536

__device__ __forceinline__ void ldsm4t(uint32_t* r, uint32_t addr) {
    asm volatile("ldmatrix.sync.aligned.m8n8.x4.trans.shared.b16 {%0,%1,%2,%3}, [%4];"
                 : "=r"(r[0]), "=r"(r[1]), "=r"(r[2]), "=r"(r[3]) : "r"(addr));
}

__device__ __forceinline__ void mma_bf16(float* d, const uint32_t* a,
                                         uint32_t b0, uint32_t b1) {
    asm volatile(
        "mma.sync.aligned.m16n8k16.row.col.f32.bf16.bf16.f32 "
        "{%0,%1,%2,%3}, {%4,%5,%6,%7}, {%8,%9}, {%0,%1,%2,%3};"
        : "+f"(d[0]), "+f"(d[1]), "+f"(d[2]), "+f"(d[3])
        : "r"(a[0]), "r"(a[1]), "r"(a[2]), "r"(a[3]), "r"(b0), "r"(b1));
}

// Non-returning vector atomic add (sm_90+).
__device__ __forceinline__ void red_add_v2(float* p, float a, float b) {
    asm volatile("red.global.add.v2.f32 [%0], {%1, %2};"
                 :: "l"(p), "f"(a), "f"(b) : "memory");
}

// ---------------------------------------------------------------------------
// Kernel 1: convert(+diag) -> tensor-core P = H^T H + 2 H^T L -> red.v2 merge.
// A-side uses ONLY hi fragments; B-side hi and 2*lo. 16 warps:
// warp w owns rows [(w&7)*16, +16) x cols [(w>>3)*64, +64).
// ---------------------------------------------------------------------------
__global__ __launch_bounds__(NTHREADS, 1)
void gram_diag(const float* __restrict__ X, const float* __restrict__ Y) {
    extern __shared__ char smem[];
    const uint32_t sb = smem_u32(smem);
    const int tid  = threadIdx.x;
    const int w    = tid >> 5;
    const int lane = tid & 31;

    const bool isX  = blockIdx.x < (NBLOCKS / 2);
    const int chunk = isX ? blockIdx.x : blockIdx.x - NBLOCKS / 2;
    const float* base  = (isX ? X : Y) + (size_t)chunk * CHUNK * DIM;
    const float* ybase = Y + (size_t)chunk * CHUNK * DIM;   // diag (X blocks)

    // ldmatrix per-lane tile-row selectors
    const int lr    = lane & 7;
    const int a_kad = (lane & 16) ? 8 : 0;
    const int a_mad = (lane & 8)  ? 8 : 0;
    const int b_kad = (lane & 8)  ? 8 : 0;
    const int b_nad = (lane & 16) ? 8 : 0;
    const int m0    = (w & 7) * 16;        // warp's output row slab
    const int nbase = (w >> 3) * 64;       // warp's output column half

    // ---- convert fp32 -> bf16 hi and 2*lo tiles; X blocks also do diag ----
    float s2 = 0.0f, s3 = 0.0f;
    #pragma unroll
    for (int it = 0; it < 8; ++it) {
        const int r = w + 16 * it;                    // sample row
        const float4 v = *reinterpret_cast<const float4*>(base + r * DIM + lane * 4);
        __nv_bfloat162 h01 = __floats2bfloat162_rn(v.x, v.y);
        __nv_bfloat162 h23 = __floats2bfloat162_rn(v.z, v.w);
        __nv_bfloat162 l01 = __floats2bfloat162_rn(2.0f * (v.x - __bfloat162float(h01.x)),
                                                   2.0f * (v.y - __bfloat162float(h01.y)));
        __nv_bfloat162 l23 = __floats2bfloat162_rn(2.0f * (v.z - __bfloat162float(h23.x)),
                                                   2.0f * (v.w - __bfloat162float(h23.y)));
        const uint32_t o = toff(r, lane * 4);
        uint2 hv, lv;
        hv.x = *reinterpret_cast<uint32_t*>(&h01);
        hv.y = *reinterpret_cast<uint32_t*>(&h23);
        lv.x = *reinterpret_cast<uint32_t*>(&l01);
        lv.y = *reinterpret_cast<uint32_t*>(&l23);
        *reinterpret_cast<uint2*>(smem + o)          = hv;
        *reinterpret_cast<uint2*>(smem + LO_OFF + o) = lv;

        if (isX) {                                    // diag: d_r = <x_r, y_r>
            const float4 u = *reinterpret_cast<const float4*>(ybase + r * DIM + lane * 4);
            float d = v.x * u.x + v.y * u.y + v.z * u.z + v.w * u.w;
            #pragma unroll
            for (int o2 = 16; o2; o2 >>= 1) d += __shfl_xor_sync(0xffffffffu, d, o2);
            s3 += d;
            s2 += d * d;
        }
    }
    if (isX && lane == 0) {
        atomicAdd(&g_S3, s3);
        atomicAdd(&g_S2, s2);
    }
    __syncthreads();

    // ---- MMA mainloop: P = H^T H + H^T (2L); A-frags hi only ----
    float acc[8][4];
    #pragma unroll
    for (int nt = 0; nt < 8; ++nt)
        #pragma unroll
        for (int i = 0; i < 4; ++i) acc[nt][i] = 0.0f;

    for (int ks = 0; ks < 8; ++ks) {
        const int k0 = ks * 16;
        uint32_t ahi[4];
        ldsm4t(ahi, sb + toff(k0 + lr + a_kad, m0 + a_mad));

        #pragma unroll
        for (int ntp = 0; ntp < 4; ++ntp) {
            const int n0 = nbase + ntp * 16;
            uint32_t bhi[4], blo[4];
            const uint32_t boff = toff(k0 + lr + b_kad, n0 + b_nad);
            ldsm4t(bhi, sb + boff);
            ldsm4t(blo, sb + LO_OFF + boff);
            mma_bf16(acc[2 * ntp],     ahi, bhi[0], bhi[1]);
            mma_bf16(acc[2 * ntp],     ahi, blo[0], blo[1]);
            mma_bf16(acc[2 * ntp + 1], ahi, bhi[2], bhi[3]);
            mma_bf16(acc[2 * ntp + 1], ahi, blo[2], blo[3]);
        }
    }

    // ---- merge partial P with v2 vector atomics; kernel end = sync ----
    float* G = g_G[isX ? 0 : 1];
    const int row0 = m0 + (lane >> 2);
    const int col0 = (lane & 3) * 2;
    #pragma unroll
    for (int nt = 0; nt < 8; ++nt) {
        const int cc = nbase + nt * 8 + col0;
        red_add_v2(&G[row0 * DIM + cc],       acc[nt][0], acc[nt][1]);
        red_add_v2(&G[(row0 + 8) * DIM + cc], acc[nt][2], acc[nt][3]);
    }
}

// ---------------------------------------------------------------------------
// Kernel 2: 16 blocks x 256. Each block dots+zeros its own 1/16 slice of
// P0/P1, float-atomics the partial into g_S1; ticket-last combines + resets.
// ---------------------------------------------------------------------------
__global__ __launch_bounds__(256, 1)
void finalize(float* __restrict__ out) {
    __shared__ float    wsum[8];
    __shared__ unsigned s_last;
    const int tid  = threadIdx.x;
    const int lane = tid & 31;
    const int w    = tid >> 5;
    const int i    = blockIdx.x * 256 + tid;   // float4 index (4096 per matrix)

    const float4* G0 = reinterpret_cast<const float4*>(g_G[0]);
    const float4* G1 = reinterpret_cast<const float4*>(g_G[1]);
    const float4 a = G0[i], b = G1[i];
    float s1 = a.x * b.x + a.y * b.y + a.z * b.z + a.w * b.w;

    // zero own slice (only this block touches these addresses)
    const float4 z = make_float4(0.f, 0.f, 0.f, 0.f);
    reinterpret_cast<float4*>(g_G[0])[i] = z;
    reinterpret_cast<float4*>(g_G[1])[i] = z;

    #pragma unroll
    for (int o = 16; o; o >>= 1) s1 += __shfl_xor_sync(0xffffffffu, s1, o);
    if (lane == 0) wsum[w] = s1;
    __syncthreads();

    if (tid == 0) {
        float t = 0.0f;
        #pragma unroll
        for (int k = 0; k < 8; ++k) t += wsum[k];
        atomicAdd(&g_S1, t);
        __threadfence();
        s_last = atomicAdd(&g_ticket, 1u);
        if (s_last == FIN_BLOCKS - 1) {
            const float S1 = atomicAdd(&g_S1, 0.0f);   // coherent read
            const double loss =
                ((double)S1 - (double)g_S2) / ((double)NROWS * (double)(NROWS - 1))
                - 2.0 * (double)g_S3 / (double)NROWS;
            out[0] = (float)loss;
            g_S1 = 0.0f; g_S2 = 0.0f; g_S3 = 0.0f; g_ticket = 0u;
        }
    }
}

// ---------------------------------------------------------------------------
extern "C" void kernel_launch(void* const* d_in, const int* in_sizes, int n_in,
                              void* d_out, int out_size) {
    const float* X = (const float*)d_in[0];
    const float* Y = (const float*)d_in[1];
    float* out = (float*)d_out;

    static bool attr_set = false;   // idempotent host-side attribute
    if (!attr_set) {
        cudaFuncSetAttribute(gram_diag,
                             cudaFuncAttributeMaxDynamicSharedMemorySize, SMEM_TOTAL);
        attr_set = true;
    }

    gram_diag<<<NBLOCKS, NTHREADS, SMEM_TOTAL>>>(X, Y);
    finalize<<<FIN_BLOCKS, 256>>>(out);
}